// round 3
// baseline (speedup 1.0000x reference)
#include <cuda_runtime.h>
#include <cuda_bf16.h>
#include <math_constants.h>

// Problem constants (fixed by the reference)
#define BB 200000
#define KK 30
#define DD 64
#define WARPS_PER_BLOCK 8
#define THREADS (WARPS_PER_BLOCK * 32)

// out[b,d] = sum_k softmax_j( exp(-sd^2/2) @ kernel + bias )[k] * context[b,k,d]
__global__ __launch_bounds__(THREADS)
void Attention_42279658062045_kernel(const float* __restrict__ sd,     // [B,K]
                                     const float* __restrict__ ctx,    // [B,K,D]
                                     const float* __restrict__ kern,   // [K,K]
                                     const float* __restrict__ bias,   // [K]
                                     float* __restrict__ out)          // [B,D]
{
    __shared__ float kS[KK * KK];
    __shared__ float bS[KK];
    __shared__ float simiS[WARPS_PER_BLOCK][KK];
    __shared__ float wS[WARPS_PER_BLOCK][KK];

    const int tid = threadIdx.x;

    // Stage the tiny kernel matrix + bias in shared (once per block; L2-hot globally)
    for (int i = tid; i < KK * KK; i += THREADS) kS[i] = kern[i];
    if (tid < KK) bS[tid] = bias[tid];
    __syncthreads();

    const int warp = tid >> 5;
    const int lane = tid & 31;
    const long long b = (long long)blockIdx.x * WARPS_PER_BLOCK + warp;
    if (b >= BB) return;

    // ---- 1) Gaussian compatibility: simi = exp(-d^2/2), lanes 0..29 ----
    float simi = 0.0f;
    if (lane < KK) {
        float d = sd[b * KK + lane];
        simi = __expf(-0.5f * d * d);
    }
    if (lane < KK) simiS[warp][lane] = simi;
    __syncwarp();

    // ---- 2) logits_j = bias_j + sum_k simi_k * kernel[k,j]  (lane j) ----
    float logit = -CUDART_INF_F;
    if (lane < KK) {
        logit = bS[lane];
        #pragma unroll
        for (int k = 0; k < KK; k++)
            logit = fmaf(simiS[warp][k], kS[k * KK + lane], logit);
    }

    // ---- 3) softmax over 30 lanes (butterfly reductions over full warp) ----
    float m = logit;
    #pragma unroll
    for (int off = 16; off; off >>= 1)
        m = fmaxf(m, __shfl_xor_sync(0xffffffffu, m, off));
    float e = (lane < KK) ? __expf(logit - m) : 0.0f;
    float s = e;
    #pragma unroll
    for (int off = 16; off; off >>= 1)
        s += __shfl_xor_sync(0xffffffffu, s, off);
    if (lane < KK) wS[warp][lane] = e / s;
    __syncwarp();

    // ---- 4) weighted aggregation over context: each lane owns 2 d-columns ----
    // float2 per lane -> one fully-coalesced 256B load per k-step per warp.
    const float2* cp = reinterpret_cast<const float2*>(ctx + b * (long long)(KK * DD)) + lane;
    float2 acc = make_float2(0.0f, 0.0f);
    #pragma unroll
    for (int k = 0; k < KK; k++) {
        float w = wS[warp][k];                 // smem broadcast, conflict-free
        float2 c = cp[k * (DD / 2)];
        acc.x = fmaf(w, c.x, acc.x);
        acc.y = fmaf(w, c.y, acc.y);
    }
    reinterpret_cast<float2*>(out + b * (long long)DD)[lane] = acc;
}

extern "C" void kernel_launch(void* const* d_in, const int* in_sizes, int n_in,
                              void* d_out, int out_size)
{
    const float* sd   = (const float*)d_in[0];  // source_distance [B,K]
    const float* ctx  = (const float*)d_in[1];  // context         [B,K,D]
    const float* kern = (const float*)d_in[2];  // kernel          [K,K]
    const float* bias = (const float*)d_in[3];  // bias            [K]
    float* out = (float*)d_out;                 // [B,D]

    const int grid = (BB + WARPS_PER_BLOCK - 1) / WARPS_PER_BLOCK;  // 25000
    Attention_42279658062045_kernel<<<grid, THREADS>>>(sd, ctx, kern, bias, out);
}

// round 4
// speedup vs baseline: 1.0106x; 1.0106x over previous
#include <cuda_runtime.h>
#include <cuda_bf16.h>
#include <math_constants.h>

// Problem constants (fixed by the reference)
#define BB 200000
#define KK 30
#define DD 64
#define WARPS_PER_BLOCK 8
#define THREADS (WARPS_PER_BLOCK * 32)

// out[b,d] = sum_k softmax_j( exp(-sd^2/2) @ kernel + bias )[k] * context[b,k,d]
__global__ __launch_bounds__(THREADS)
void Attention_42279658062045_kernel(const float* __restrict__ sd,     // [B,K]
                                     const float* __restrict__ ctx,    // [B,K,D]
                                     const float* __restrict__ kern,   // [K,K]
                                     const float* __restrict__ bias,   // [K]
                                     float* __restrict__ out)          // [B,D]
{
    __shared__ float kS[KK * KK];
    __shared__ float bS[KK];
    __shared__ float simiS[WARPS_PER_BLOCK][KK];
    __shared__ float wS[WARPS_PER_BLOCK][KK];

    const int tid = threadIdx.x;

    // Stage the tiny kernel matrix + bias in shared (once per block; L2-hot globally)
    for (int i = tid; i < KK * KK; i += THREADS) kS[i] = kern[i];
    if (tid < KK) bS[tid] = bias[tid];
    __syncthreads();

    const int warp = tid >> 5;
    const int lane = tid & 31;
    const long long b = (long long)blockIdx.x * WARPS_PER_BLOCK + warp;
    if (b >= BB) return;

    // ---- 1) Gaussian compatibility: simi = exp(-d^2/2), lanes 0..29 ----
    float simi = 0.0f;
    if (lane < KK) {
        float d = sd[b * KK + lane];
        simi = __expf(-0.5f * d * d);
        simiS[warp][lane] = simi;
    }
    __syncwarp();

    // ---- 2) logits_j = bias_j + sum_k simi_k * kernel[k,j]  (lane j) ----
    float logit = -CUDART_INF_F;
    if (lane < KK) {
        logit = bS[lane];
        #pragma unroll
        for (int k = 0; k < KK; k++)
            logit = fmaf(simiS[warp][k], kS[k * KK + lane], logit);
    }

    // ---- 3) softmax over 30 lanes (butterfly reductions over full warp) ----
    float m = logit;
    #pragma unroll
    for (int off = 16; off; off >>= 1)
        m = fmaxf(m, __shfl_xor_sync(0xffffffffu, m, off));
    float e = (lane < KK) ? __expf(logit - m) : 0.0f;
    float s = e;
    #pragma unroll
    for (int off = 16; off; off >>= 1)
        s += __shfl_xor_sync(0xffffffffu, s, off);
    if (lane < KK) wS[warp][lane] = e / s;
    __syncwarp();

    // ---- 4) weighted aggregation with LDG.128 ----
    // Row = 30*64 floats = 480 float4. float4 index i = t*32 + lane decomposes as
    //   k = 2t + (lane>=16),  d-block = (lane&15)*4   (fixed per lane).
    // Lanes 0-15 accumulate even k, lanes 16-31 odd k; fold with shfl_xor(16).
    const float4* cp4 = reinterpret_cast<const float4*>(ctx + b * (long long)(KK * DD)) + lane;
    const int parity = lane >> 4;                 // 0: even k, 1: odd k
    float4 acc = make_float4(0.f, 0.f, 0.f, 0.f);
    #pragma unroll
    for (int t = 0; t < KK / 2; t++) {            // 15 iterations
        float  w = wS[warp][2 * t + parity];      // smem broadcast per half-warp
        float4 c = __ldcs(cp4 + t * 32);          // streaming: no reuse, evict-first
        acc.x = fmaf(w, c.x, acc.x);
        acc.y = fmaf(w, c.y, acc.y);
        acc.z = fmaf(w, c.z, acc.z);
        acc.w = fmaf(w, c.w, acc.w);
    }
    // Fold odd-k half into even-k half (lane l += lane l^16)
    acc.x += __shfl_xor_sync(0xffffffffu, acc.x, 16);
    acc.y += __shfl_xor_sync(0xffffffffu, acc.y, 16);
    acc.z += __shfl_xor_sync(0xffffffffu, acc.z, 16);
    acc.w += __shfl_xor_sync(0xffffffffu, acc.w, 16);

    if (lane < 16) {
        float4* op4 = reinterpret_cast<float4*>(out + b * (long long)DD);
        __stcs(op4 + lane, acc);                  // STG.128, streaming
    }
}

extern "C" void kernel_launch(void* const* d_in, const int* in_sizes, int n_in,
                              void* d_out, int out_size)
{
    const float* sd   = (const float*)d_in[0];  // source_distance [B,K]
    const float* ctx  = (const float*)d_in[1];  // context         [B,K,D]
    const float* kern = (const float*)d_in[2];  // kernel          [K,K]
    const float* bias = (const float*)d_in[3];  // bias            [K]
    float* out = (float*)d_out;                 // [B,D]

    const int grid = (BB + WARPS_PER_BLOCK - 1) / WARPS_PER_BLOCK;  // 25000
    Attention_42279658062045_kernel<<<grid, THREADS>>>(sd, ctx, kern, bias, out);
}